// round 14
// baseline (speedup 1.0000x reference)
#include <cuda_runtime.h>
#include <cuda_fp16.h>
#include <math.h>
#include <stdint.h>

#define Bsz 4
#define Nn 2048
#define Ee 128
#define Kk 3072            // C*P
#define Mm 16384           // 2*B*N rows (sig half then mem half)
#define HALF_WIN 15
#define NCHUNK 48          // 3072 / 64

// ---------------- scratch ----------------
__device__ float g_embed[Mm * Ee];           // pre-BN y = conv(x)+bias
__device__ float g_psum[128 * Ee];           // per-GEMM-CTA column sums
__device__ float g_psumsq[128 * Ee];
__device__ float g_attn_band[Bsz * Nn * 32];
__device__ uint4 g_w0u[49152];               // W main bf16, CHUNK-major [48][128 rows][8 uint4]
__device__ uint4 g_w1u[49152];               // W residual bf16, same layout

// ---------------- helpers ----------------
__device__ __forceinline__ uint32_t smem_u32(const void* p) {
    uint32_t a;
    asm("{ .reg .u64 t; cvta.to.shared.u64 t, %1; cvt.u32.u64 %0, t; }" : "=r"(a) : "l"(p));
    return a;
}
__device__ __forceinline__ void ldsm4(uint32_t addr, uint32_t* r) {
    asm volatile("ldmatrix.sync.aligned.m8n8.x4.shared.b16 {%0,%1,%2,%3}, [%4];"
                 : "=r"(r[0]), "=r"(r[1]), "=r"(r[2]), "=r"(r[3]) : "r"(addr));
}
__device__ __forceinline__ void ldsm2t(uint32_t addr, uint32_t* r) {
    asm volatile("ldmatrix.sync.aligned.m8n8.x2.trans.shared.b16 {%0,%1}, [%2];"
                 : "=r"(r[0]), "=r"(r[1]) : "r"(addr));
}
__device__ __forceinline__ void mma16816(float* c, const uint32_t* a, const uint32_t* b) {
    asm volatile(
        "mma.sync.aligned.m16n8k16.row.col.f32.bf16.bf16.f32 "
        "{%0,%1,%2,%3}, {%4,%5,%6,%7}, {%8,%9}, {%0,%1,%2,%3};"
        : "+f"(c[0]), "+f"(c[1]), "+f"(c[2]), "+f"(c[3])
        : "r"(a[0]), "r"(a[1]), "r"(a[2]), "r"(a[3]), "r"(b[0]), "r"(b[1]));
}
__device__ __forceinline__ void mma16816h(float* c, const uint32_t* a, const uint32_t* b) {
    asm volatile(
        "mma.sync.aligned.m16n8k16.row.col.f32.f16.f16.f32 "
        "{%0,%1,%2,%3}, {%4,%5,%6,%7}, {%8,%9}, {%0,%1,%2,%3};"
        : "+f"(c[0]), "+f"(c[1]), "+f"(c[2]), "+f"(c[3])
        : "r"(a[0]), "r"(a[1]), "r"(a[2]), "r"(a[3]), "r"(b[0]), "r"(b[1]));
}
#define CP_ASYNC16(dst, src) \
    asm volatile("cp.async.ca.shared.global [%0], [%1], 16;" :: "r"(dst), "l"(src) : "memory")
#define CP_COMMIT  asm volatile("cp.async.commit_group;" ::: "memory")
#define CP_WAIT0   asm volatile("cp.async.wait_group 0;" ::: "memory")
#define NBAR_SYNC(id)   asm volatile("bar.sync %0, 384;" :: "r"(id) : "memory")
#define NBAR_ARRIVE(id) asm volatile("bar.arrive %0, 384;" :: "r"(id) : "memory")
// barrier ids: FULL = 1+s (1..3), EMPTY = 4+s (4..6)

__device__ __forceinline__ uint32_t sw128(uint32_t o) { return o ^ ((o >> 3) & 0x70); }

__device__ __forceinline__ void split4(float4 v, uint32_t& m0, uint32_t& m1,
                                       uint32_t& r0, uint32_t& r1) {
    asm("cvt.rn.bf16x2.f32 %0, %1, %2;" : "=r"(m0) : "f"(v.y), "f"(v.x));
    asm("cvt.rn.bf16x2.f32 %0, %1, %2;" : "=r"(m1) : "f"(v.w), "f"(v.z));
    float e0 = v.x - __uint_as_float(m0 << 16);
    float e1 = v.y - __uint_as_float(m0 & 0xffff0000u);
    float e2 = v.z - __uint_as_float(m1 << 16);
    float e3 = v.w - __uint_as_float(m1 & 0xffff0000u);
    asm("cvt.rn.bf16x2.f32 %0, %1, %2;" : "=r"(r0) : "f"(e1), "f"(e0));
    asm("cvt.rn.bf16x2.f32 %0, %1, %2;" : "=r"(r1) : "f"(e3), "f"(e2));
}

// ---------------- K0: pre-split W into bf16 main + residual (chunk-major) ----
__global__ void k_wsplit(const float* __restrict__ w) {
    int t = blockIdx.x * blockDim.x + threadIdx.x;
    int row = t / 384;
    int kq = t - row * 384;
    int chunk = kq >> 3;
    int piece = kq & 7;
    int out = chunk * 1024 + row * 8 + piece;
    const float* src = w + (size_t)row * Kk + kq * 8;
    float4 u = *(const float4*)src;
    float4 v = *(const float4*)(src + 4);
    uint32_t m0, m1, m2, m3, r0, r1, r2, r3;
    split4(u, m0, m1, r0, r1);
    split4(v, m2, m3, r2, r3);
    g_w0u[out] = make_uint4(m0, m1, m2, m3);
    g_w1u[out] = make_uint4(r0, r1, r2, r3);
}

// ---------------- K1: warp-specialized HMMA GEMM + fused BN stats -----------
// 12 warps: wid 0-7 consumers (64x32 tiles), wid 8-11 producers. 3 stages.
#define ST_SZ 65536
#define OA0 0
#define OA1 16384
#define OB0 32768
#define OB1 49152
#define GEMM_SMEM (1024 + 3 * ST_SZ + 2048)

__global__ void __launch_bounds__(384, 1)
k_gemm(const float* __restrict__ sig, const float* __restrict__ mem,
       const float* __restrict__ bias) {
    extern __shared__ char smraw[];
    uint32_t sb = smem_u32(smraw);
    uint32_t ab = (sb + 1023) & ~1023u;
    char* sm = smraw + (ab - sb);

    int tid = threadIdx.x;
    int wid = tid >> 5, lane = tid & 31;

    int bm = blockIdx.x * 128;
    const float* X = (bm < 8192) ? sig : mem;
    int rb = (bm < 8192) ? bm : bm - 8192;

    float* bn_s = (float*)(sm + 3 * ST_SZ);        // [8 warps][4 tn][8]
    float* bn_q = bn_s + 256;

    if (wid >= 8) {
        // ================= PRODUCER (4 warps) =================
        int pt = tid - 256;         // 0..127
        int prow = pt >> 4;
        int pf4 = pt & 15;
        const float* Xb = X + (size_t)rb * Kk + pf4 * 4;

        int s = 0;
        for (int c = 0; c < NCHUNK; c++) {
            uint32_t base = ab + s * ST_SZ;
            char* smA0 = sm + s * ST_SZ + OA0;
            char* smA1 = sm + s * ST_SZ + OA1;
            if (c >= 3) NBAR_SYNC(4 + s);

            const uint4* w0c = g_w0u + c * 1024;
            const uint4* w1c = g_w1u + c * 1024;
#pragma unroll
            for (int q = 0; q < 8; q++) {
                int idx = q * 128 + pt;
                uint32_t off = sw128((uint32_t)(idx >> 3) * 128 + (idx & 7) * 16);
                CP_ASYNC16(base + OB0 + off, w0c + idx);
                CP_ASYNC16(base + OB1 + off, w1c + idx);
            }
            CP_COMMIT;

            const float* src = Xb + c * 64;
#pragma unroll
            for (int batch = 0; batch < 2; batch++) {
                float4 v[8];
#pragma unroll
                for (int i = 0; i < 8; i++) {
                    int r = (batch * 8 + i) * 8 + prow;
                    v[i] = *(const float4*)(src + (size_t)r * Kk);
                }
#pragma unroll
                for (int i = 0; i < 8; i++) {
                    int r = (batch * 8 + i) * 8 + prow;
                    uint32_t o = sw128((uint32_t)r * 128 + pf4 * 8);
                    uint32_t m0, m1, r0, r1;
                    split4(v[i], m0, m1, r0, r1);
                    *(uint2*)(smA0 + o) = make_uint2(m0, m1);
                    *(uint2*)(smA1 + o) = make_uint2(r0, r1);
                }
            }
            CP_WAIT0;
            asm volatile("membar.cta;" ::: "memory");
            NBAR_ARRIVE(1 + s);
            s = (s == 2) ? 0 : s + 1;
        }
    } else {
        // ================= CONSUMER (8 warps, 64x32 each) =================
        int mrow = (wid >> 2) * 64;      // 0 or 64
        int ncolw = (wid & 3) * 32;      // 0,32,64,96

        float acc[4][4][4];
#pragma unroll
        for (int a = 0; a < 4; a++)
#pragma unroll
            for (int b = 0; b < 4; b++)
#pragma unroll
                for (int c = 0; c < 4; c++) acc[a][b][c] = 0.f;

        uint32_t arow_off[4], brow_off[2];
#pragma unroll
        for (int mi = 0; mi < 4; mi++)
            arow_off[mi] = (uint32_t)(mrow + mi * 16 + (lane & 15)) * 128 + ((lane >> 4) << 4);
#pragma unroll
        for (int p = 0; p < 2; p++)
            brow_off[p] = (uint32_t)(ncolw + p * 16 + (lane & 7) + ((lane >> 4) << 3)) * 128
                          + (((lane >> 3) & 1) << 4);

        int s = 0;
        for (int c = 0; c < NCHUNK; c++) {
            uint32_t base = ab + s * ST_SZ;
            NBAR_SYNC(1 + s);
#pragma unroll
            for (int j = 0; j < 4; j++) {
                uint32_t fa0[4][4], fa1[4][4], fb0[2][4], fb1[2][4];
#pragma unroll
                for (int mi = 0; mi < 4; mi++) {
                    uint32_t off = sw128(arow_off[mi] + j * 32);
                    ldsm4(base + OA0 + off, fa0[mi]);
                    ldsm4(base + OA1 + off, fa1[mi]);
                }
#pragma unroll
                for (int p = 0; p < 2; p++) {
                    uint32_t off = sw128(brow_off[p] + j * 32);
                    ldsm4(base + OB0 + off, fb0[p]);
                    ldsm4(base + OB1 + off, fb1[p]);
                }
                // term-major: 16 independent accumulators per term
#pragma unroll
                for (int mi = 0; mi < 4; mi++)
#pragma unroll
                    for (int p = 0; p < 2; p++)
#pragma unroll
                        for (int hh = 0; hh < 2; hh++)
                            mma16816(acc[mi][2 * p + hh], fa0[mi], &fb0[p][2 * hh]);
#pragma unroll
                for (int mi = 0; mi < 4; mi++)
#pragma unroll
                    for (int p = 0; p < 2; p++)
#pragma unroll
                        for (int hh = 0; hh < 2; hh++)
                            mma16816(acc[mi][2 * p + hh], fa1[mi], &fb0[p][2 * hh]);
#pragma unroll
                for (int mi = 0; mi < 4; mi++)
#pragma unroll
                    for (int p = 0; p < 2; p++)
#pragma unroll
                        for (int hh = 0; hh < 2; hh++)
                            mma16816(acc[mi][2 * p + hh], fa0[mi], &fb1[p][2 * hh]);
            }
            NBAR_ARRIVE(4 + s);
            s = (s == 2) ? 0 : s + 1;
        }

        // epilogue: +bias, store, BN column partials (per warp over its 64 rows)
        int g = lane >> 2, t4 = lane & 3;
#pragma unroll
        for (int tn = 0; tn < 4; tn++) {
            int col = ncolw + tn * 8 + 2 * t4;
            float bx = __ldg(&bias[col]);
            float by = __ldg(&bias[col + 1]);
            float sx = 0.f, sy = 0.f, qx = 0.f, qy = 0.f;
#pragma unroll
            for (int mi = 0; mi < 4; mi++) {
                int row0 = bm + mrow + mi * 16 + g;
                float o0 = acc[mi][tn][0] + bx;
                float o1 = acc[mi][tn][1] + by;
                float o2 = acc[mi][tn][2] + bx;
                float o3 = acc[mi][tn][3] + by;
                *(float2*)&g_embed[(size_t)row0 * Ee + col] = make_float2(o0, o1);
                *(float2*)&g_embed[(size_t)(row0 + 8) * Ee + col] = make_float2(o2, o3);
                sx += o0 + o2; sy += o1 + o3;
                qx += o0 * o0 + o2 * o2; qy += o1 * o1 + o3 * o3;
            }
#pragma unroll
            for (int msk = 4; msk < 32; msk <<= 1) {
                sx += __shfl_xor_sync(0xffffffffu, sx, msk);
                sy += __shfl_xor_sync(0xffffffffu, sy, msk);
                qx += __shfl_xor_sync(0xffffffffu, qx, msk);
                qy += __shfl_xor_sync(0xffffffffu, qy, msk);
            }
            if ((lane >> 2) == 0) {
                bn_s[(wid * 4 + tn) * 8 + 2 * t4] = sx;
                bn_s[(wid * 4 + tn) * 8 + 2 * t4 + 1] = sy;
                bn_q[(wid * 4 + tn) * 8 + 2 * t4] = qx;
                bn_q[(wid * 4 + tn) * 8 + 2 * t4 + 1] = qy;
            }
        }
    }
    __syncthreads();
    if (tid < 128) {
        int e = tid;
        int n = e >> 5;              // N quarter (0..3)
        int tn = (e >> 3) & 3;
        int k = e & 7;
        float s = bn_s[((n)*4 + tn) * 8 + k] + bn_s[((n + 4) * 4 + tn) * 8 + k];
        float q = bn_q[((n)*4 + tn) * 8 + k] + bn_q[((n + 4) * 4 + tn) * 8 + k];
        g_psum[blockIdx.x * 128 + e] = s;
        g_psumsq[blockIdx.x * 128 + e] = q;
    }
}

// ---------------- K4: banded sim + softmax, 16 rows/block, 512 threads ------
__global__ void __launch_bounds__(512)
k_attn(const float* __restrict__ gamma, const float* __restrict__ beta,
       float* __restrict__ out_attn) {
    __shared__ float s_et[46 * 129];
    __shared__ float s_ex[16 * 128];
    __shared__ float s_band[16][32];
    __shared__ float s_sc[256], s_sh[256];
    int i0 = blockIdx.x * 16;
    int b = blockIdx.y;
    int jmin = max(0, i0 - HALF_WIN);
    int jmax = min(Nn - 1, i0 + 15 + HALF_WIN);
    int nj = jmax - jmin + 1;   // <= 46
    int tid = threadIdx.x;

    if (tid < 256) {
        int half = tid >> 7;
        int e = tid & 127;
        float s = 0.f, sq = 0.f;
#pragma unroll 8
        for (int c = 0; c < 64; c++) {
            s += g_psum[(half * 64 + c) * Ee + e];
            sq += g_psumsq[(half * 64 + c) * Ee + e];
        }
        float mean = s / 8192.f;
        float var = sq / 8192.f - mean * mean;
        float rstd = rsqrtf(var + 1e-5f);
        float sc = rstd * __ldg(&gamma[e]);
        s_sc[tid] = sc;
        s_sh[tid] = __ldg(&beta[e]) - mean * sc;
    }
    __syncthreads();

    for (int p = tid; p < nj * 128; p += 512) {
        int jr = p >> 7, k = p & 127;
        float v = g_embed[(size_t)(8192 + b * Nn + jmin + jr) * Ee + k] * s_sc[128 + k] + s_sh[128 + k];
        s_et[jr * 129 + k] = (v >= 0.f) ? v : 0.1f * v;
    }
    for (int p = tid; p < 16 * 128; p += 512) {
        int r = p >> 7, k = p & 127;
        float v = g_embed[(size_t)(b * Nn + i0 + r) * Ee + k] * s_sc[k] + s_sh[k];
        s_ex[r * 128 + k] = (v >= 0.f) ? v : 0.1f * v;
    }
    __syncthreads();

    int w = tid >> 5, lane = tid & 31;
    int i = i0 + w;
    int j0 = max(0, i - HALF_WIN);
    int j1 = min(Nn - 1, i + HALF_WIN);
    int width = j1 - j0 + 1;

    float sim = -1e30f;
    if (lane < width) {
        int jr = j0 + lane - jmin;
        const float* ex = &s_ex[w * 128];
        const float* et = &s_et[jr * 129];
        float a0 = 0.f, a1 = 0.f, a2 = 0.f, a3 = 0.f;
#pragma unroll
        for (int k = 0; k < 128; k += 4) {
            a0 += ex[k] * et[k];
            a1 += ex[k + 1] * et[k + 1];
            a2 += ex[k + 2] * et[k + 2];
            a3 += ex[k + 3] * et[k + 3];
        }
        sim = (a0 + a1) + (a2 + a3);
    }
    float mx = sim;
#pragma unroll
    for (int o = 16; o; o >>= 1) mx = fmaxf(mx, __shfl_xor_sync(0xffffffffu, mx, o));
    float ev = (lane < width) ? expf(sim - mx) : 0.f;
    float sum = ev;
#pragma unroll
    for (int o = 16; o; o >>= 1) sum += __shfl_xor_sync(0xffffffffu, sum, o);
    float a = ev / sum;
    s_band[w][lane] = (lane < width) ? a : 0.f;
    if (lane < width) g_attn_band[(b * Nn + i) * 32 + lane] = a;
    __syncwarp();

    float* rowp = out_attn + ((size_t)(b * Nn + i)) * Nn;
#pragma unroll
    for (int t = 0; t < 16; t++) {
        int j4 = (t * 32 + lane) * 4;
        float4 o = make_float4(0.f, 0.f, 0.f, 0.f);
        if (j4 + 3 >= j0 && j4 <= j1) {
#pragma unroll
            for (int q = 0; q < 4; q++) {
                int j = j4 + q;
                if (j >= j0 && j <= j1) ((float*)&o)[q] = s_band[w][j - j0];
            }
        }
        *(float4*)&rowp[j4] = o;
    }
}

// ---------------- K5: banded attn @ mem, fp16 HMMA, diag windows, fc=128 ----
#define MW_A0 0
#define MW_A1 7168
#define MW_M  14336
#define MW_SMEM (14336 + 26112 + 256)

__global__ void __launch_bounds__(256, 4)
k_memw(const float* __restrict__ sig, const float* __restrict__ mem,
       float* __restrict__ out_mem) {
    extern __shared__ char smw[];
    uint32_t mwb = smem_u32(smw);
    int i0 = blockIdx.x * 64;
    int fc = blockIdx.y * 128;
    int b = blockIdx.z;
    int tid = threadIdx.x;
    int jv = i0 - HALF_WIN;

    __half* s_a0 = (__half*)(smw + MW_A0);   // [64][56]
    __half* s_a1 = (__half*)(smw + MW_A1);
    __half* s_m  = (__half*)(smw + MW_M);    // [96][136]

#pragma unroll
    for (int q = 0; q < 14; q++) {
        int p = q * 256 + tid;
        if (p < 3584) ((uint32_t*)smw)[p] = 0u;
    }
    __syncthreads();

#pragma unroll
    for (int q8 = 0; q8 < 8; q8++) {
        int q = q8 * 256 + tid;
        int r = q >> 5, l = q & 31;
        int i = i0 + r;
        int j0 = max(0, i - HALF_WIN);
        int j1 = min(Nn - 1, i + HALF_WIN);
        if (l <= j1 - j0) {
            float a = g_attn_band[(b * Nn + i) * 32 + l];
            __half a0 = __float2half_rn(a);
            float res = a - __half2float(a0);
            int col = (j0 + l) - jv - (r & ~15);
            s_a0[r * 56 + col] = a0;
            s_a1[r * 56 + col] = __float2half_rn(res);
        }
    }
    {
        float4 v[12];
#pragma unroll
        for (int q = 0; q < 12; q++) {
            int p = q * 256 + tid;
            int row = p >> 5;
            int f4 = (p & 31) * 4;
            int ja = jv + row;
            if (ja >= 0 && ja < Nn)
                v[q] = *(const float4*)&mem[(size_t)(b * Nn + ja) * Kk + fc + f4];
            else
                v[q] = make_float4(0.f, 0.f, 0.f, 0.f);
        }
#pragma unroll
        for (int q = 0; q < 12; q++) {
            int p = q * 256 + tid;
            int row = p >> 5;
            int f4 = (p & 31) * 4;
            *(__half2*)&s_m[row * 136 + f4] = __floats2half2_rn(v[q].x, v[q].y);
            *(__half2*)&s_m[row * 136 + f4 + 2] = __floats2half2_rn(v[q].z, v[q].w);
        }
    }
    __syncthreads();

    int wid = tid >> 5, lane = tid & 31;
    uint32_t a0b = mwb + MW_A0;
    uint32_t a1b = mwb + MW_A1;
    uint32_t mb = mwb + MW_M;

    float acc[4][2][4];
#pragma unroll
    for (int mi = 0; mi < 4; mi++)
#pragma unroll
        for (int t = 0; t < 2; t++)
#pragma unroll
            for (int c = 0; c < 4; c++) acc[mi][t][c] = 0.f;

#pragma unroll
    for (int q = 0; q < 6; q++) {
        uint32_t fb[2][2];
        uint32_t krow = q * 16 + (lane & 15);
#pragma unroll
        for (int t = 0; t < 2; t++) {
            uint32_t ncol = (wid * 2 + t) * 8;
            ldsm2t(mb + (krow * 136 + ncol) * 2, fb[t]);
        }
        int mlo = (q - 2 > 0) ? q - 2 : 0;
        int mhi = (q < 3) ? q : 3;
#pragma unroll
        for (int mi = 0; mi < 4; mi++) {
            if (mi < mlo || mi > mhi) continue;
            int ks = q - mi;
            uint32_t row = mi * 16 + (lane & 15);
            uint32_t col = ks * 16 + ((lane >> 4) << 3);
            uint32_t fa0[4], fa1[4];
            ldsm4(a0b + (row * 56 + col) * 2, fa0);
            ldsm4(a1b + (row * 56 + col) * 2, fa1);
#pragma unroll
            for (int t = 0; t < 2; t++) {
                mma16816h(acc[mi][t], fa0, fb[t]);
                mma16816h(acc[mi][t], fa1, fb[t]);
            }
        }
    }

    int g = lane >> 2, t4 = lane & 3;
#pragma unroll
    for (int mi = 0; mi < 4; mi++) {
#pragma unroll
        for (int t = 0; t < 2; t++) {
            int col = wid * 16 + t * 8 + 2 * t4;
            int row0 = i0 + mi * 16 + g;
            size_t base0 = (size_t)(b * Nn + row0) * Kk + fc + col;
            size_t base1 = (size_t)(b * Nn + row0 + 8) * Kk + fc + col;
            float2 sg0 = *(const float2*)&sig[base0];
            float2 sg1 = *(const float2*)&sig[base1];
            float2 o0 = make_float2(0.5f * sg0.x + 0.5f * acc[mi][t][0],
                                    0.5f * sg0.y + 0.5f * acc[mi][t][1]);
            float2 o1 = make_float2(0.5f * sg1.x + 0.5f * acc[mi][t][2],
                                    0.5f * sg1.y + 0.5f * acc[mi][t][3]);
            *(float2*)&out_mem[base0] = o0;
            *(float2*)&out_mem[base1] = o1;
        }
    }
}

// ---------------- launch ----------------
extern "C" void kernel_launch(void* const* d_in, const int* in_sizes, int n_in,
                              void* d_out, int out_size) {
    const float* sig   = (const float*)d_in[0];
    const float* mem   = (const float*)d_in[1];
    const float* w     = (const float*)d_in[2];
    const float* bias  = (const float*)d_in[3];
    const float* gamma = (const float*)d_in[4];
    const float* beta  = (const float*)d_in[5];
    float* out_mem  = (float*)d_out;
    float* out_attn = (float*)d_out + (size_t)Bsz * Nn * Kk;

    static bool attr_done = false;
    if (!attr_done) {
        cudaFuncSetAttribute(k_gemm, cudaFuncAttributeMaxDynamicSharedMemorySize, GEMM_SMEM);
        cudaFuncSetAttribute(k_memw, cudaFuncAttributeMaxDynamicSharedMemorySize, MW_SMEM);
        attr_done = true;
    }

    k_wsplit<<<192, 256>>>(w);                               // launch 0
    k_gemm<<<Mm / 128, 384, GEMM_SMEM>>>(sig, mem, bias);    // launch 1
    k_attn<<<dim3(Nn / 16, Bsz), 512>>>(gamma, beta, out_attn); // launch 2
    k_memw<<<dim3(Nn / 64, 24, Bsz), 256, MW_SMEM>>>(sig, mem, out_mem); // launch 3
}

// round 15
// speedup vs baseline: 1.5077x; 1.5077x over previous
#include <cuda_runtime.h>
#include <cuda_fp16.h>
#include <math.h>
#include <stdint.h>

#define Bsz 4
#define Nn 2048
#define Ee 128
#define Kk 3072            // C*P
#define Mm 16384           // 2*B*N rows (sig half then mem half)
#define HALF_WIN 15
#define NCHUNK 48          // 3072 / 64

// ---------------- scratch ----------------
__device__ float g_embed[Mm * Ee];           // pre-BN y = conv(x)+bias
__device__ float g_psum[128 * Ee];           // per-GEMM-CTA column sums
__device__ float g_psumsq[128 * Ee];
__device__ float g_attn_band[Bsz * Nn * 32];
__device__ uint4 g_w0u[49152];               // W main bf16, CHUNK-major [48][128 rows][8 uint4]
__device__ uint4 g_w1u[49152];               // W residual bf16, same layout

// ---------------- helpers ----------------
__device__ __forceinline__ uint32_t smem_u32(const void* p) {
    uint32_t a;
    asm("{ .reg .u64 t; cvta.to.shared.u64 t, %1; cvt.u32.u64 %0, t; }" : "=r"(a) : "l"(p));
    return a;
}
__device__ __forceinline__ void ldsm4(uint32_t addr, uint32_t* r) {
    asm volatile("ldmatrix.sync.aligned.m8n8.x4.shared.b16 {%0,%1,%2,%3}, [%4];"
                 : "=r"(r[0]), "=r"(r[1]), "=r"(r[2]), "=r"(r[3]) : "r"(addr));
}
__device__ __forceinline__ void ldsm2t(uint32_t addr, uint32_t* r) {
    asm volatile("ldmatrix.sync.aligned.m8n8.x2.trans.shared.b16 {%0,%1}, [%2];"
                 : "=r"(r[0]), "=r"(r[1]) : "r"(addr));
}
__device__ __forceinline__ void mma16816(float* c, const uint32_t* a, const uint32_t* b) {
    asm volatile(
        "mma.sync.aligned.m16n8k16.row.col.f32.bf16.bf16.f32 "
        "{%0,%1,%2,%3}, {%4,%5,%6,%7}, {%8,%9}, {%0,%1,%2,%3};"
        : "+f"(c[0]), "+f"(c[1]), "+f"(c[2]), "+f"(c[3])
        : "r"(a[0]), "r"(a[1]), "r"(a[2]), "r"(a[3]), "r"(b[0]), "r"(b[1]));
}
__device__ __forceinline__ void mma16816h(float* c, const uint32_t* a, const uint32_t* b) {
    asm volatile(
        "mma.sync.aligned.m16n8k16.row.col.f32.f16.f16.f32 "
        "{%0,%1,%2,%3}, {%4,%5,%6,%7}, {%8,%9}, {%0,%1,%2,%3};"
        : "+f"(c[0]), "+f"(c[1]), "+f"(c[2]), "+f"(c[3])
        : "r"(a[0]), "r"(a[1]), "r"(a[2]), "r"(a[3]), "r"(b[0]), "r"(b[1]));
}
#define CP_ASYNC16(dst, src) \
    asm volatile("cp.async.ca.shared.global [%0], [%1], 16;" :: "r"(dst), "l"(src) : "memory")
#define CP_COMMIT  asm volatile("cp.async.commit_group;" ::: "memory")
#define CP_WAIT0   asm volatile("cp.async.wait_group 0;" ::: "memory")
#define NBAR_SYNC(id)   asm volatile("bar.sync %0, 256;" :: "r"(id) : "memory")
#define NBAR_ARRIVE(id) asm volatile("bar.arrive %0, 256;" :: "r"(id) : "memory")
// barrier ids: FULL = 1+s (1..3), EMPTY = 4+s (4..6)

__device__ __forceinline__ uint32_t sw128(uint32_t o) { return o ^ ((o >> 3) & 0x70); }

__device__ __forceinline__ void split4(float4 v, uint32_t& m0, uint32_t& m1,
                                       uint32_t& r0, uint32_t& r1) {
    asm("cvt.rn.bf16x2.f32 %0, %1, %2;" : "=r"(m0) : "f"(v.y), "f"(v.x));
    asm("cvt.rn.bf16x2.f32 %0, %1, %2;" : "=r"(m1) : "f"(v.w), "f"(v.z));
    float e0 = v.x - __uint_as_float(m0 << 16);
    float e1 = v.y - __uint_as_float(m0 & 0xffff0000u);
    float e2 = v.z - __uint_as_float(m1 << 16);
    float e3 = v.w - __uint_as_float(m1 & 0xffff0000u);
    asm("cvt.rn.bf16x2.f32 %0, %1, %2;" : "=r"(r0) : "f"(e1), "f"(e0));
    asm("cvt.rn.bf16x2.f32 %0, %1, %2;" : "=r"(r1) : "f"(e3), "f"(e2));
}

// ---------------- K0: pre-split W into bf16 main + residual (chunk-major) ----
__global__ void k_wsplit(const float* __restrict__ w) {
    int t = blockIdx.x * blockDim.x + threadIdx.x;
    int row = t / 384;
    int kq = t - row * 384;
    int chunk = kq >> 3;
    int piece = kq & 7;
    int out = chunk * 1024 + row * 8 + piece;
    const float* src = w + (size_t)row * Kk + kq * 8;
    float4 u = *(const float4*)src;
    float4 v = *(const float4*)(src + 4);
    uint32_t m0, m1, m2, m3, r0, r1, r2, r3;
    split4(u, m0, m1, r0, r1);
    split4(v, m2, m3, r2, r3);
    g_w0u[out] = make_uint4(m0, m1, m2, m3);
    g_w1u[out] = make_uint4(r0, r1, r2, r3);
}

// ---------------- K1: warp-specialized HMMA GEMM + fused BN stats -----------
// 8 warps: wid 0-3 consumers (64x64 tiles), wid 4-7 producers. 3 stages.
#define ST_SZ 65536
#define OA0 0
#define OA1 16384
#define OB0 32768
#define OB1 49152
#define GEMM_SMEM (1024 + 3 * ST_SZ + 2048)

__global__ void __launch_bounds__(256, 1)
k_gemm(const float* __restrict__ sig, const float* __restrict__ mem,
       const float* __restrict__ bias) {
    extern __shared__ char smraw[];
    uint32_t sb = smem_u32(smraw);
    uint32_t ab = (sb + 1023) & ~1023u;
    char* sm = smraw + (ab - sb);

    int tid = threadIdx.x;
    int wid = tid >> 5, lane = tid & 31;

    int bm = blockIdx.x * 128;
    const float* X = (bm < 8192) ? sig : mem;
    int rb = (bm < 8192) ? bm : bm - 8192;

    float* bn_s = (float*)(sm + 3 * ST_SZ);        // [4][8][8]
    float* bn_q = bn_s + 256;

    if (wid >= 4) {
        // ================= PRODUCER =================
        int pt = tid - 128;
        int prow = pt >> 4;
        int pf4 = pt & 15;
        const float* Xb = X + (size_t)rb * Kk + pf4 * 4;

        int s = 0;
        for (int c = 0; c < NCHUNK; c++) {
            uint32_t base = ab + s * ST_SZ;
            char* smA0 = sm + s * ST_SZ + OA0;
            char* smA1 = sm + s * ST_SZ + OA1;
            if (c >= 3) NBAR_SYNC(4 + s);

            const uint4* w0c = g_w0u + c * 1024;
            const uint4* w1c = g_w1u + c * 1024;
#pragma unroll
            for (int q = 0; q < 8; q++) {
                int idx = q * 128 + pt;
                uint32_t off = sw128((uint32_t)(idx >> 3) * 128 + (idx & 7) * 16);
                CP_ASYNC16(base + OB0 + off, w0c + idx);
                CP_ASYNC16(base + OB1 + off, w1c + idx);
            }
            CP_COMMIT;

            const float* src = Xb + c * 64;
#pragma unroll
            for (int batch = 0; batch < 2; batch++) {
                float4 v[8];
#pragma unroll
                for (int i = 0; i < 8; i++) {
                    int r = (batch * 8 + i) * 8 + prow;
                    v[i] = *(const float4*)(src + (size_t)r * Kk);
                }
#pragma unroll
                for (int i = 0; i < 8; i++) {
                    int r = (batch * 8 + i) * 8 + prow;
                    uint32_t o = sw128((uint32_t)r * 128 + pf4 * 8);
                    uint32_t m0, m1, r0, r1;
                    split4(v[i], m0, m1, r0, r1);
                    *(uint2*)(smA0 + o) = make_uint2(m0, m1);
                    *(uint2*)(smA1 + o) = make_uint2(r0, r1);
                }
            }
            CP_WAIT0;
            asm volatile("membar.cta;" ::: "memory");
            NBAR_ARRIVE(1 + s);
            s = (s == 2) ? 0 : s + 1;
        }
    } else {
        // ================= CONSUMER =================
        int mrow = (wid >> 1) * 64;
        int ncolw = (wid & 1) * 64;

        float acc[4][8][4];
#pragma unroll
        for (int a = 0; a < 4; a++)
#pragma unroll
            for (int b = 0; b < 8; b++)
#pragma unroll
                for (int c = 0; c < 4; c++) acc[a][b][c] = 0.f;

        uint32_t arow_off[4], brow_off[4];
#pragma unroll
        for (int mi = 0; mi < 4; mi++)
            arow_off[mi] = (uint32_t)(mrow + mi * 16 + (lane & 15)) * 128 + ((lane >> 4) << 4);
#pragma unroll
        for (int p = 0; p < 4; p++)
            brow_off[p] = (uint32_t)(ncolw + p * 16 + (lane & 7) + ((lane >> 4) << 3)) * 128
                          + (((lane >> 3) & 1) << 4);

        int s = 0;
        for (int c = 0; c < NCHUNK; c++) {
            uint32_t base = ab + s * ST_SZ;
            NBAR_SYNC(1 + s);
#pragma unroll
            for (int j = 0; j < 4; j++) {
                uint32_t fa0[4][4], fa1[4][4], fb0[4][4], fb1[4][4];
#pragma unroll
                for (int mi = 0; mi < 4; mi++) {
                    uint32_t off = sw128(arow_off[mi] + j * 32);
                    ldsm4(base + OA0 + off, fa0[mi]);
                    ldsm4(base + OA1 + off, fa1[mi]);
                }
#pragma unroll
                for (int p = 0; p < 4; p++) {
                    uint32_t off = sw128(brow_off[p] + j * 32);
                    ldsm4(base + OB0 + off, fb0[p]);
                    ldsm4(base + OB1 + off, fb1[p]);
                }
#pragma unroll
                for (int mi = 0; mi < 4; mi++)
#pragma unroll
                    for (int p = 0; p < 4; p++)
#pragma unroll
                        for (int hh = 0; hh < 2; hh++)
                            mma16816(acc[mi][2 * p + hh], fa0[mi], &fb0[p][2 * hh]);
#pragma unroll
                for (int mi = 0; mi < 4; mi++)
#pragma unroll
                    for (int p = 0; p < 4; p++)
#pragma unroll
                        for (int hh = 0; hh < 2; hh++)
                            mma16816(acc[mi][2 * p + hh], fa1[mi], &fb0[p][2 * hh]);
#pragma unroll
                for (int mi = 0; mi < 4; mi++)
#pragma unroll
                    for (int p = 0; p < 4; p++)
#pragma unroll
                        for (int hh = 0; hh < 2; hh++)
                            mma16816(acc[mi][2 * p + hh], fa0[mi], &fb1[p][2 * hh]);
            }
            NBAR_ARRIVE(4 + s);
            s = (s == 2) ? 0 : s + 1;
        }

        int g = lane >> 2, t4 = lane & 3;
#pragma unroll
        for (int tn = 0; tn < 8; tn++) {
            int col = ncolw + tn * 8 + 2 * t4;
            float bx = __ldg(&bias[col]);
            float by = __ldg(&bias[col + 1]);
            float sx = 0.f, sy = 0.f, qx = 0.f, qy = 0.f;
#pragma unroll
            for (int mi = 0; mi < 4; mi++) {
                int row0 = bm + mrow + mi * 16 + g;
                float o0 = acc[mi][tn][0] + bx;
                float o1 = acc[mi][tn][1] + by;
                float o2 = acc[mi][tn][2] + bx;
                float o3 = acc[mi][tn][3] + by;
                *(float2*)&g_embed[(size_t)row0 * Ee + col] = make_float2(o0, o1);
                *(float2*)&g_embed[(size_t)(row0 + 8) * Ee + col] = make_float2(o2, o3);
                sx += o0 + o2; sy += o1 + o3;
                qx += o0 * o0 + o2 * o2; qy += o1 * o1 + o3 * o3;
            }
#pragma unroll
            for (int msk = 4; msk < 32; msk <<= 1) {
                sx += __shfl_xor_sync(0xffffffffu, sx, msk);
                sy += __shfl_xor_sync(0xffffffffu, sy, msk);
                qx += __shfl_xor_sync(0xffffffffu, qx, msk);
                qy += __shfl_xor_sync(0xffffffffu, qy, msk);
            }
            if ((lane >> 2) == 0) {
                bn_s[(wid * 8 + tn) * 8 + 2 * t4] = sx;
                bn_s[(wid * 8 + tn) * 8 + 2 * t4 + 1] = sy;
                bn_q[(wid * 8 + tn) * 8 + 2 * t4] = qx;
                bn_q[(wid * 8 + tn) * 8 + 2 * t4 + 1] = qy;
            }
        }
    }
    __syncthreads();
    if (tid < 128) {
        int e = tid;
        int tn = (e & 63) >> 3, k = e & 7;
        int w0 = (e >> 6);
        float s = bn_s[((w0)*8 + tn) * 8 + k] + bn_s[((w0 + 2) * 8 + tn) * 8 + k];
        float q = bn_q[((w0)*8 + tn) * 8 + k] + bn_q[((w0 + 2) * 8 + tn) * 8 + k];
        g_psum[blockIdx.x * 128 + e] = s;
        g_psumsq[blockIdx.x * 128 + e] = q;
    }
}

// ---------------- K4: banded sim + softmax (BN finalize + apply folded) ----
__global__ void k_attn(const float* __restrict__ gamma, const float* __restrict__ beta,
                       float* __restrict__ out_attn) {
    __shared__ float s_et[38 * 129];
    __shared__ float s_ex[8 * 128];
    __shared__ float s_band[8][32];
    __shared__ float s_sc[256], s_sh[256];
    int i0 = blockIdx.x * 8;
    int b = blockIdx.y;
    int jmin = max(0, i0 - HALF_WIN);
    int jmax = min(Nn - 1, i0 + 7 + HALF_WIN);
    int nj = jmax - jmin + 1;
    int tid = threadIdx.x;

    {
        int half = tid >> 7;
        int e = tid & 127;
        float s = 0.f, sq = 0.f;
#pragma unroll 8
        for (int c = 0; c < 64; c++) {
            s += g_psum[(half * 64 + c) * Ee + e];
            sq += g_psumsq[(half * 64 + c) * Ee + e];
        }
        float mean = s / 8192.f;
        float var = sq / 8192.f - mean * mean;
        float rstd = rsqrtf(var + 1e-5f);
        float sc = rstd * __ldg(&gamma[e]);
        s_sc[tid] = sc;
        s_sh[tid] = __ldg(&beta[e]) - mean * sc;
    }
    __syncthreads();

    for (int p = tid; p < nj * 128; p += 256) {
        int jr = p >> 7, k = p & 127;
        float v = g_embed[(size_t)(8192 + b * Nn + jmin + jr) * Ee + k] * s_sc[128 + k] + s_sh[128 + k];
        s_et[jr * 129 + k] = (v >= 0.f) ? v : 0.1f * v;
    }
    for (int p = tid; p < 8 * 128; p += 256) {
        int r = p >> 7, k = p & 127;
        float v = g_embed[(size_t)(b * Nn + i0 + r) * Ee + k] * s_sc[k] + s_sh[k];
        s_ex[r * 128 + k] = (v >= 0.f) ? v : 0.1f * v;
    }
    __syncthreads();

    int w = tid >> 5, lane = tid & 31;
    int i = i0 + w;
    int j0 = max(0, i - HALF_WIN);
    int j1 = min(Nn - 1, i + HALF_WIN);
    int width = j1 - j0 + 1;

    float sim = -1e30f;
    if (lane < width) {
        int jr = j0 + lane - jmin;
        const float* ex = &s_ex[w * 128];
        const float* et = &s_et[jr * 129];
        float a0 = 0.f, a1 = 0.f, a2 = 0.f, a3 = 0.f;
#pragma unroll
        for (int k = 0; k < 128; k += 4) {
            a0 += ex[k] * et[k];
            a1 += ex[k + 1] * et[k + 1];
            a2 += ex[k + 2] * et[k + 2];
            a3 += ex[k + 3] * et[k + 3];
        }
        sim = (a0 + a1) + (a2 + a3);
    }
    float mx = sim;
#pragma unroll
    for (int o = 16; o; o >>= 1) mx = fmaxf(mx, __shfl_xor_sync(0xffffffffu, mx, o));
    float ev = (lane < width) ? expf(sim - mx) : 0.f;
    float sum = ev;
#pragma unroll
    for (int o = 16; o; o >>= 1) sum += __shfl_xor_sync(0xffffffffu, sum, o);
    float a = ev / sum;
    s_band[w][lane] = (lane < width) ? a : 0.f;
    if (lane < width) g_attn_band[(b * Nn + i) * 32 + lane] = a;
    __syncwarp();

    float* rowp = out_attn + ((size_t)(b * Nn + i)) * Nn;
#pragma unroll
    for (int t = 0; t < 16; t++) {
        int j4 = (t * 32 + lane) * 4;
        float4 o = make_float4(0.f, 0.f, 0.f, 0.f);
        if (j4 + 3 >= j0 && j4 <= j1) {
#pragma unroll
            for (int q = 0; q < 4; q++) {
                int j = j4 + q;
                if (j >= j0 && j <= j1) ((float*)&o)[q] = s_band[w][j - j0];
            }
        }
        *(float4*)&rowp[j4] = o;
    }
}

// ---------------- K5: banded attn @ mem, fp16 HMMA, diag windows, fc=128 ----
#define MW_A0 0
#define MW_A1 7168
#define MW_M  14336
#define MW_SMEM (14336 + 26112 + 256)

__global__ void __launch_bounds__(256, 4)
k_memw(const float* __restrict__ sig, const float* __restrict__ mem,
       float* __restrict__ out_mem) {
    extern __shared__ char smw[];
    uint32_t mwb = smem_u32(smw);
    int i0 = blockIdx.x * 64;
    int fc = blockIdx.y * 128;
    int b = blockIdx.z;
    int tid = threadIdx.x;
    int jv = i0 - HALF_WIN;

    __half* s_a0 = (__half*)(smw + MW_A0);   // [64][56]
    __half* s_a1 = (__half*)(smw + MW_A1);
    __half* s_m  = (__half*)(smw + MW_M);    // [96][136]

#pragma unroll
    for (int q = 0; q < 14; q++) {
        int p = q * 256 + tid;
        ((uint32_t*)smw)[p] = 0u;
    }
    __syncthreads();

#pragma unroll
    for (int q8 = 0; q8 < 8; q8++) {
        int q = q8 * 256 + tid;
        int r = q >> 5, l = q & 31;
        int i = i0 + r;
        int j0 = max(0, i - HALF_WIN);
        int j1 = min(Nn - 1, i + HALF_WIN);
        if (l <= j1 - j0) {
            float a = g_attn_band[(b * Nn + i) * 32 + l];
            __half a0 = __float2half_rn(a);
            float res = a - __half2float(a0);
            int col = (j0 + l) - jv - (r & ~15);
            s_a0[r * 56 + col] = a0;
            s_a1[r * 56 + col] = __float2half_rn(res);
        }
    }
    {
        float4 v[12];
#pragma unroll
        for (int q = 0; q < 12; q++) {
            int p = q * 256 + tid;
            int row = p >> 5;
            int f4 = (p & 31) * 4;
            int ja = jv + row;
            if (ja >= 0 && ja < Nn)
                v[q] = *(const float4*)&mem[(size_t)(b * Nn + ja) * Kk + fc + f4];
            else
                v[q] = make_float4(0.f, 0.f, 0.f, 0.f);
        }
#pragma unroll
        for (int q = 0; q < 12; q++) {
            int p = q * 256 + tid;
            int row = p >> 5;
            int f4 = (p & 31) * 4;
            *(__half2*)&s_m[row * 136 + f4] = __floats2half2_rn(v[q].x, v[q].y);
            *(__half2*)&s_m[row * 136 + f4 + 2] = __floats2half2_rn(v[q].z, v[q].w);
        }
    }
    __syncthreads();

    int wid = tid >> 5, lane = tid & 31;
    uint32_t a0b = mwb + MW_A0;
    uint32_t a1b = mwb + MW_A1;
    uint32_t mb = mwb + MW_M;

    float acc[4][2][4];
#pragma unroll
    for (int mi = 0; mi < 4; mi++)
#pragma unroll
        for (int t = 0; t < 2; t++)
#pragma unroll
            for (int c = 0; c < 4; c++) acc[mi][t][c] = 0.f;

#pragma unroll
    for (int q = 0; q < 6; q++) {
        uint32_t fb[2][2];
        uint32_t krow = q * 16 + (lane & 15);
#pragma unroll
        for (int t = 0; t < 2; t++) {
            uint32_t ncol = (wid * 2 + t) * 8;
            ldsm2t(mb + (krow * 136 + ncol) * 2, fb[t]);
        }
        int mlo = (q - 2 > 0) ? q - 2 : 0;
        int mhi = (q < 3) ? q : 3;
#pragma unroll
        for (int mi = 0; mi < 4; mi++) {
            if (mi < mlo || mi > mhi) continue;
            int ks = q - mi;
            uint32_t row = mi * 16 + (lane & 15);
            uint32_t col = ks * 16 + ((lane >> 4) << 3);
            uint32_t fa0[4], fa1[4];
            ldsm4(a0b + (row * 56 + col) * 2, fa0);
            ldsm4(a1b + (row * 56 + col) * 2, fa1);
#pragma unroll
            for (int t = 0; t < 2; t++) {
                mma16816h(acc[mi][t], fa0, fb[t]);
                mma16816h(acc[mi][t], fa1, fb[t]);
            }
        }
    }

    int g = lane >> 2, t4 = lane & 3;
#pragma unroll
    for (int mi = 0; mi < 4; mi++) {
#pragma unroll
        for (int t = 0; t < 2; t++) {
            int col = wid * 16 + t * 8 + 2 * t4;
            int row0 = i0 + mi * 16 + g;
            size_t base0 = (size_t)(b * Nn + row0) * Kk + fc + col;
            size_t base1 = (size_t)(b * Nn + row0 + 8) * Kk + fc + col;
            float2 sg0 = *(const float2*)&sig[base0];
            float2 sg1 = *(const float2*)&sig[base1];
            float2 o0 = make_float2(0.5f * sg0.x + 0.5f * acc[mi][t][0],
                                    0.5f * sg0.y + 0.5f * acc[mi][t][1]);
            float2 o1 = make_float2(0.5f * sg1.x + 0.5f * acc[mi][t][2],
                                    0.5f * sg1.y + 0.5f * acc[mi][t][3]);
            *(float2*)&out_mem[base0] = o0;
            *(float2*)&out_mem[base1] = o1;
        }
    }
}

// ---------------- launch ----------------
extern "C" void kernel_launch(void* const* d_in, const int* in_sizes, int n_in,
                              void* d_out, int out_size) {
    const float* sig   = (const float*)d_in[0];
    const float* mem   = (const float*)d_in[1];
    const float* w     = (const float*)d_in[2];
    const float* bias  = (const float*)d_in[3];
    const float* gamma = (const float*)d_in[4];
    const float* beta  = (const float*)d_in[5];
    float* out_mem  = (float*)d_out;
    float* out_attn = (float*)d_out + (size_t)Bsz * Nn * Kk;

    static bool attr_done = false;
    if (!attr_done) {
        cudaFuncSetAttribute(k_gemm, cudaFuncAttributeMaxDynamicSharedMemorySize, GEMM_SMEM);
        cudaFuncSetAttribute(k_memw, cudaFuncAttributeMaxDynamicSharedMemorySize, MW_SMEM);
        attr_done = true;
    }

    k_wsplit<<<192, 256>>>(w);                               // launch 0
    k_gemm<<<Mm / 128, 256, GEMM_SMEM>>>(sig, mem, bias);    // launch 1
    k_attn<<<dim3(Nn / 8, Bsz), 256>>>(gamma, beta, out_attn); // launch 2
    k_memw<<<dim3(Nn / 64, 24, Bsz), 256, MW_SMEM>>>(sig, mem, out_mem); // launch 3
}

// round 16
// speedup vs baseline: 1.5150x; 1.0048x over previous
#include <cuda_runtime.h>
#include <cuda_fp16.h>
#include <math.h>
#include <stdint.h>

#define Bsz 4
#define Nn 2048
#define Ee 128
#define Kk 3072            // C*P
#define Mm 16384           // 2*B*N rows (sig half then mem half)
#define HALF_WIN 15
#define NCHUNK 48          // 3072 / 64

// ---------------- scratch ----------------
__device__ float g_embed[Mm * Ee];           // pre-BN y = conv(x)+bias
__device__ float g_psum[128 * Ee];           // per-GEMM-CTA column sums
__device__ float g_psumsq[128 * Ee];
__device__ float g_attn_band[Bsz * Nn * 32];
__device__ uint4 g_w0u[49152];               // W main bf16, CHUNK-major [48][128 rows][8 uint4]
__device__ uint4 g_w1u[49152];               // W residual bf16, same layout

// ---------------- helpers ----------------
__device__ __forceinline__ uint32_t smem_u32(const void* p) {
    uint32_t a;
    asm("{ .reg .u64 t; cvta.to.shared.u64 t, %1; cvt.u32.u64 %0, t; }" : "=r"(a) : "l"(p));
    return a;
}
__device__ __forceinline__ void ldsm4(uint32_t addr, uint32_t* r) {
    asm volatile("ldmatrix.sync.aligned.m8n8.x4.shared.b16 {%0,%1,%2,%3}, [%4];"
                 : "=r"(r[0]), "=r"(r[1]), "=r"(r[2]), "=r"(r[3]) : "r"(addr));
}
__device__ __forceinline__ void ldsm2t(uint32_t addr, uint32_t* r) {
    asm volatile("ldmatrix.sync.aligned.m8n8.x2.trans.shared.b16 {%0,%1}, [%2];"
                 : "=r"(r[0]), "=r"(r[1]) : "r"(addr));
}
__device__ __forceinline__ void mma16816(float* c, const uint32_t* a, const uint32_t* b) {
    asm volatile(
        "mma.sync.aligned.m16n8k16.row.col.f32.bf16.bf16.f32 "
        "{%0,%1,%2,%3}, {%4,%5,%6,%7}, {%8,%9}, {%0,%1,%2,%3};"
        : "+f"(c[0]), "+f"(c[1]), "+f"(c[2]), "+f"(c[3])
        : "r"(a[0]), "r"(a[1]), "r"(a[2]), "r"(a[3]), "r"(b[0]), "r"(b[1]));
}
__device__ __forceinline__ void mma16816h(float* c, const uint32_t* a, const uint32_t* b) {
    asm volatile(
        "mma.sync.aligned.m16n8k16.row.col.f32.f16.f16.f32 "
        "{%0,%1,%2,%3}, {%4,%5,%6,%7}, {%8,%9}, {%0,%1,%2,%3};"
        : "+f"(c[0]), "+f"(c[1]), "+f"(c[2]), "+f"(c[3])
        : "r"(a[0]), "r"(a[1]), "r"(a[2]), "r"(a[3]), "r"(b[0]), "r"(b[1]));
}
#define CP_ASYNC16(dst, src) \
    asm volatile("cp.async.ca.shared.global [%0], [%1], 16;" :: "r"(dst), "l"(src) : "memory")
#define CP_COMMIT  asm volatile("cp.async.commit_group;" ::: "memory")
#define CP_WAIT0   asm volatile("cp.async.wait_group 0;" ::: "memory")
#define NBAR_SYNC(id)   asm volatile("bar.sync %0, 256;" :: "r"(id) : "memory")
#define NBAR_ARRIVE(id) asm volatile("bar.arrive %0, 256;" :: "r"(id) : "memory")
// barrier ids: FULL = 1+s (1..3), EMPTY = 4+s (4..6)

__device__ __forceinline__ uint32_t sw128(uint32_t o) { return o ^ ((o >> 3) & 0x70); }

__device__ __forceinline__ void split4(float4 v, uint32_t& m0, uint32_t& m1,
                                       uint32_t& r0, uint32_t& r1) {
    asm("cvt.rn.bf16x2.f32 %0, %1, %2;" : "=r"(m0) : "f"(v.y), "f"(v.x));
    asm("cvt.rn.bf16x2.f32 %0, %1, %2;" : "=r"(m1) : "f"(v.w), "f"(v.z));
    float e0 = v.x - __uint_as_float(m0 << 16);
    float e1 = v.y - __uint_as_float(m0 & 0xffff0000u);
    float e2 = v.z - __uint_as_float(m1 << 16);
    float e3 = v.w - __uint_as_float(m1 & 0xffff0000u);
    asm("cvt.rn.bf16x2.f32 %0, %1, %2;" : "=r"(r0) : "f"(e1), "f"(e0));
    asm("cvt.rn.bf16x2.f32 %0, %1, %2;" : "=r"(r1) : "f"(e3), "f"(e2));
}

// ---------------- K0: pre-split W into bf16 main + residual (chunk-major) ----
__global__ void k_wsplit(const float* __restrict__ w) {
    int t = blockIdx.x * blockDim.x + threadIdx.x;
    int row = t / 384;
    int kq = t - row * 384;
    int chunk = kq >> 3;
    int piece = kq & 7;
    int out = chunk * 1024 + row * 8 + piece;
    const float* src = w + (size_t)row * Kk + kq * 8;
    float4 u = *(const float4*)src;
    float4 v = *(const float4*)(src + 4);
    uint32_t m0, m1, m2, m3, r0, r1, r2, r3;
    split4(u, m0, m1, r0, r1);
    split4(v, m2, m3, r2, r3);
    g_w0u[out] = make_uint4(m0, m1, m2, m3);
    g_w1u[out] = make_uint4(r0, r1, r2, r3);
}

// ---------------- K1: warp-specialized HMMA GEMM + fused BN stats -----------
// 8 warps: wid 0-3 consumers (64x64 tiles), wid 4-7 producers. 3 stages.
#define ST_SZ 65536
#define OA0 0
#define OA1 16384
#define OB0 32768
#define OB1 49152
#define GEMM_SMEM (1024 + 3 * ST_SZ + 2048)

__global__ void __launch_bounds__(256, 1)
k_gemm(const float* __restrict__ sig, const float* __restrict__ mem,
       const float* __restrict__ bias) {
    extern __shared__ char smraw[];
    uint32_t sb = smem_u32(smraw);
    uint32_t ab = (sb + 1023) & ~1023u;
    char* sm = smraw + (ab - sb);

    int tid = threadIdx.x;
    int wid = tid >> 5, lane = tid & 31;

    int bm = blockIdx.x * 128;
    const float* X = (bm < 8192) ? sig : mem;
    int rb = (bm < 8192) ? bm : bm - 8192;

    float* bn_s = (float*)(sm + 3 * ST_SZ);        // [4][8][8]
    float* bn_q = bn_s + 256;

    if (wid >= 4) {
        // ================= PRODUCER =================
        int pt = tid - 128;
        int prow = pt >> 4;
        int pf4 = pt & 15;
        const float* Xb = X + (size_t)rb * Kk + pf4 * 4;

        int s = 0;
        for (int c = 0; c < NCHUNK; c++) {
            uint32_t base = ab + s * ST_SZ;
            char* smA0 = sm + s * ST_SZ + OA0;
            char* smA1 = sm + s * ST_SZ + OA1;
            if (c >= 3) NBAR_SYNC(4 + s);

            const uint4* w0c = g_w0u + c * 1024;
            const uint4* w1c = g_w1u + c * 1024;
#pragma unroll
            for (int q = 0; q < 8; q++) {
                int idx = q * 128 + pt;
                uint32_t off = sw128((uint32_t)(idx >> 3) * 128 + (idx & 7) * 16);
                CP_ASYNC16(base + OB0 + off, w0c + idx);
                CP_ASYNC16(base + OB1 + off, w1c + idx);
            }
            CP_COMMIT;

            const float* src = Xb + c * 64;
#pragma unroll
            for (int batch = 0; batch < 2; batch++) {
                float4 v[8];
#pragma unroll
                for (int i = 0; i < 8; i++) {
                    int r = (batch * 8 + i) * 8 + prow;
                    v[i] = *(const float4*)(src + (size_t)r * Kk);
                }
#pragma unroll
                for (int i = 0; i < 8; i++) {
                    int r = (batch * 8 + i) * 8 + prow;
                    uint32_t o = sw128((uint32_t)r * 128 + pf4 * 8);
                    uint32_t m0, m1, r0, r1;
                    split4(v[i], m0, m1, r0, r1);
                    *(uint2*)(smA0 + o) = make_uint2(m0, m1);
                    *(uint2*)(smA1 + o) = make_uint2(r0, r1);
                }
            }
            CP_WAIT0;
            asm volatile("membar.cta;" ::: "memory");
            NBAR_ARRIVE(1 + s);
            s = (s == 2) ? 0 : s + 1;
        }
    } else {
        // ================= CONSUMER =================
        int mrow = (wid >> 1) * 64;
        int ncolw = (wid & 1) * 64;

        float acc[4][8][4];
#pragma unroll
        for (int a = 0; a < 4; a++)
#pragma unroll
            for (int b = 0; b < 8; b++)
#pragma unroll
                for (int c = 0; c < 4; c++) acc[a][b][c] = 0.f;

        uint32_t arow_off[4], brow_off[4];
#pragma unroll
        for (int mi = 0; mi < 4; mi++)
            arow_off[mi] = (uint32_t)(mrow + mi * 16 + (lane & 15)) * 128 + ((lane >> 4) << 4);
#pragma unroll
        for (int p = 0; p < 4; p++)
            brow_off[p] = (uint32_t)(ncolw + p * 16 + (lane & 7) + ((lane >> 4) << 3)) * 128
                          + (((lane >> 3) & 1) << 4);

        int s = 0;
        for (int c = 0; c < NCHUNK; c++) {
            uint32_t base = ab + s * ST_SZ;
            NBAR_SYNC(1 + s);
#pragma unroll
            for (int j = 0; j < 4; j++) {
                uint32_t fa0[4][4], fa1[4][4], fb0[4][4], fb1[4][4];
#pragma unroll
                for (int mi = 0; mi < 4; mi++) {
                    uint32_t off = sw128(arow_off[mi] + j * 32);
                    ldsm4(base + OA0 + off, fa0[mi]);
                    ldsm4(base + OA1 + off, fa1[mi]);
                }
#pragma unroll
                for (int p = 0; p < 4; p++) {
                    uint32_t off = sw128(brow_off[p] + j * 32);
                    ldsm4(base + OB0 + off, fb0[p]);
                    ldsm4(base + OB1 + off, fb1[p]);
                }
#pragma unroll
                for (int mi = 0; mi < 4; mi++)
#pragma unroll
                    for (int p = 0; p < 4; p++)
#pragma unroll
                        for (int hh = 0; hh < 2; hh++)
                            mma16816(acc[mi][2 * p + hh], fa0[mi], &fb0[p][2 * hh]);
#pragma unroll
                for (int mi = 0; mi < 4; mi++)
#pragma unroll
                    for (int p = 0; p < 4; p++)
#pragma unroll
                        for (int hh = 0; hh < 2; hh++)
                            mma16816(acc[mi][2 * p + hh], fa1[mi], &fb0[p][2 * hh]);
#pragma unroll
                for (int mi = 0; mi < 4; mi++)
#pragma unroll
                    for (int p = 0; p < 4; p++)
#pragma unroll
                        for (int hh = 0; hh < 2; hh++)
                            mma16816(acc[mi][2 * p + hh], fa0[mi], &fb1[p][2 * hh]);
            }
            NBAR_ARRIVE(4 + s);
            s = (s == 2) ? 0 : s + 1;
        }

        int g = lane >> 2, t4 = lane & 3;
#pragma unroll
        for (int tn = 0; tn < 8; tn++) {
            int col = ncolw + tn * 8 + 2 * t4;
            float bx = __ldg(&bias[col]);
            float by = __ldg(&bias[col + 1]);
            float sx = 0.f, sy = 0.f, qx = 0.f, qy = 0.f;
#pragma unroll
            for (int mi = 0; mi < 4; mi++) {
                int row0 = bm + mrow + mi * 16 + g;
                float o0 = acc[mi][tn][0] + bx;
                float o1 = acc[mi][tn][1] + by;
                float o2 = acc[mi][tn][2] + bx;
                float o3 = acc[mi][tn][3] + by;
                *(float2*)&g_embed[(size_t)row0 * Ee + col] = make_float2(o0, o1);
                *(float2*)&g_embed[(size_t)(row0 + 8) * Ee + col] = make_float2(o2, o3);
                sx += o0 + o2; sy += o1 + o3;
                qx += o0 * o0 + o2 * o2; qy += o1 * o1 + o3 * o3;
            }
#pragma unroll
            for (int msk = 4; msk < 32; msk <<= 1) {
                sx += __shfl_xor_sync(0xffffffffu, sx, msk);
                sy += __shfl_xor_sync(0xffffffffu, sy, msk);
                qx += __shfl_xor_sync(0xffffffffu, qx, msk);
                qy += __shfl_xor_sync(0xffffffffu, qy, msk);
            }
            if ((lane >> 2) == 0) {
                bn_s[(wid * 8 + tn) * 8 + 2 * t4] = sx;
                bn_s[(wid * 8 + tn) * 8 + 2 * t4 + 1] = sy;
                bn_q[(wid * 8 + tn) * 8 + 2 * t4] = qx;
                bn_q[(wid * 8 + tn) * 8 + 2 * t4 + 1] = qy;
            }
        }
    }
    __syncthreads();
    if (tid < 128) {
        int e = tid;
        int tn = (e & 63) >> 3, k = e & 7;
        int w0 = (e >> 6);
        float s = bn_s[((w0)*8 + tn) * 8 + k] + bn_s[((w0 + 2) * 8 + tn) * 8 + k];
        float q = bn_q[((w0)*8 + tn) * 8 + k] + bn_q[((w0 + 2) * 8 + tn) * 8 + k];
        g_psum[blockIdx.x * 128 + e] = s;
        g_psumsq[blockIdx.x * 128 + e] = q;
    }
}

// ---------------- K4: banded sim + softmax, 16 rows/block (2 rows/warp) -----
__global__ void __launch_bounds__(256)
k_attn(const float* __restrict__ gamma, const float* __restrict__ beta,
       float* __restrict__ out_attn) {
    __shared__ float s_et[46 * 129];
    __shared__ float s_ex[16 * 128];
    __shared__ float s_band[16][32];
    __shared__ float s_sc[256], s_sh[256];
    int i0 = blockIdx.x * 16;
    int b = blockIdx.y;
    int jmin = max(0, i0 - HALF_WIN);
    int jmax = min(Nn - 1, i0 + 15 + HALF_WIN);
    int nj = jmax - jmin + 1;     // <= 46
    int tid = threadIdx.x;

    {
        int half = tid >> 7;
        int e = tid & 127;
        float s = 0.f, sq = 0.f;
#pragma unroll 8
        for (int c = 0; c < 64; c++) {
            s += g_psum[(half * 64 + c) * Ee + e];
            sq += g_psumsq[(half * 64 + c) * Ee + e];
        }
        float mean = s / 8192.f;
        float var = sq / 8192.f - mean * mean;
        float rstd = rsqrtf(var + 1e-5f);
        float sc = rstd * __ldg(&gamma[e]);
        s_sc[tid] = sc;
        s_sh[tid] = __ldg(&beta[e]) - mean * sc;
    }
    __syncthreads();

    for (int p = tid; p < nj * 128; p += 256) {
        int jr = p >> 7, k = p & 127;
        float v = g_embed[(size_t)(8192 + b * Nn + jmin + jr) * Ee + k] * s_sc[128 + k] + s_sh[128 + k];
        s_et[jr * 129 + k] = (v >= 0.f) ? v : 0.1f * v;
    }
    for (int p = tid; p < 16 * 128; p += 256) {
        int r = p >> 7, k = p & 127;
        float v = g_embed[(size_t)(b * Nn + i0 + r) * Ee + k] * s_sc[k] + s_sh[k];
        s_ex[r * 128 + k] = (v >= 0.f) ? v : 0.1f * v;
    }
    __syncthreads();

    int w = tid >> 5, lane = tid & 31;

#pragma unroll
    for (int rr = 0; rr < 2; rr++) {
        int r = w + rr * 8;               // row within tile
        int i = i0 + r;
        int j0 = max(0, i - HALF_WIN);
        int j1 = min(Nn - 1, i + HALF_WIN);
        int width = j1 - j0 + 1;

        float sim = -1e30f;
        if (lane < width) {
            int jr = j0 + lane - jmin;
            const float* ex = &s_ex[r * 128];
            const float* et = &s_et[jr * 129];
            float a0 = 0.f, a1 = 0.f, a2 = 0.f, a3 = 0.f;
#pragma unroll
            for (int k = 0; k < 128; k += 4) {
                a0 += ex[k] * et[k];
                a1 += ex[k + 1] * et[k + 1];
                a2 += ex[k + 2] * et[k + 2];
                a3 += ex[k + 3] * et[k + 3];
            }
            sim = (a0 + a1) + (a2 + a3);
        }
        float mx = sim;
#pragma unroll
        for (int o = 16; o; o >>= 1) mx = fmaxf(mx, __shfl_xor_sync(0xffffffffu, mx, o));
        float ev = (lane < width) ? expf(sim - mx) : 0.f;
        float sum = ev;
#pragma unroll
        for (int o = 16; o; o >>= 1) sum += __shfl_xor_sync(0xffffffffu, sum, o);
        float a = ev / sum;
        s_band[r][lane] = (lane < width) ? a : 0.f;
        if (lane < width) g_attn_band[(b * Nn + i) * 32 + lane] = a;
        __syncwarp();

        float* rowp = out_attn + ((size_t)(b * Nn + i)) * Nn;
#pragma unroll
        for (int t = 0; t < 16; t++) {
            int j4 = (t * 32 + lane) * 4;
            float4 o = make_float4(0.f, 0.f, 0.f, 0.f);
            if (j4 + 3 >= j0 && j4 <= j1) {
#pragma unroll
                for (int q = 0; q < 4; q++) {
                    int j = j4 + q;
                    if (j >= j0 && j <= j1) ((float*)&o)[q] = s_band[r][j - j0];
                }
            }
            *(float4*)&rowp[j4] = o;
        }
    }
}

// ---------------- K5: banded attn @ mem, fp16 HMMA, diag windows, fc=128 ----
#define MW_A0 0
#define MW_A1 7168
#define MW_M  14336
#define MW_SMEM (14336 + 26112 + 256)

__global__ void __launch_bounds__(256, 4)
k_memw(const float* __restrict__ sig, const float* __restrict__ mem,
       float* __restrict__ out_mem) {
    extern __shared__ char smw[];
    uint32_t mwb = smem_u32(smw);
    int i0 = blockIdx.x * 64;
    int fc = blockIdx.y * 128;
    int b = blockIdx.z;
    int tid = threadIdx.x;
    int jv = i0 - HALF_WIN;

    __half* s_a0 = (__half*)(smw + MW_A0);   // [64][56]
    __half* s_a1 = (__half*)(smw + MW_A1);
    __half* s_m  = (__half*)(smw + MW_M);    // [96][136]

#pragma unroll
    for (int q = 0; q < 14; q++) {
        int p = q * 256 + tid;
        ((uint32_t*)smw)[p] = 0u;
    }
    __syncthreads();

#pragma unroll
    for (int q8 = 0; q8 < 8; q8++) {
        int q = q8 * 256 + tid;
        int r = q >> 5, l = q & 31;
        int i = i0 + r;
        int j0 = max(0, i - HALF_WIN);
        int j1 = min(Nn - 1, i + HALF_WIN);
        if (l <= j1 - j0) {
            float a = g_attn_band[(b * Nn + i) * 32 + l];
            __half a0 = __float2half_rn(a);
            float res = a - __half2float(a0);
            int col = (j0 + l) - jv - (r & ~15);
            s_a0[r * 56 + col] = a0;
            s_a1[r * 56 + col] = __float2half_rn(res);
        }
    }
    {
        float4 v[12];
#pragma unroll
        for (int q = 0; q < 12; q++) {
            int p = q * 256 + tid;
            int row = p >> 5;
            int f4 = (p & 31) * 4;
            int ja = jv + row;
            if (ja >= 0 && ja < Nn)
                v[q] = *(const float4*)&mem[(size_t)(b * Nn + ja) * Kk + fc + f4];
            else
                v[q] = make_float4(0.f, 0.f, 0.f, 0.f);
        }
#pragma unroll
        for (int q = 0; q < 12; q++) {
            int p = q * 256 + tid;
            int row = p >> 5;
            int f4 = (p & 31) * 4;
            *(__half2*)&s_m[row * 136 + f4] = __floats2half2_rn(v[q].x, v[q].y);
            *(__half2*)&s_m[row * 136 + f4 + 2] = __floats2half2_rn(v[q].z, v[q].w);
        }
    }
    __syncthreads();

    int wid = tid >> 5, lane = tid & 31;
    uint32_t a0b = mwb + MW_A0;
    uint32_t a1b = mwb + MW_A1;
    uint32_t mb = mwb + MW_M;

    float acc[4][2][4];
#pragma unroll
    for (int mi = 0; mi < 4; mi++)
#pragma unroll
        for (int t = 0; t < 2; t++)
#pragma unroll
            for (int c = 0; c < 4; c++) acc[mi][t][c] = 0.f;

#pragma unroll
    for (int q = 0; q < 6; q++) {
        uint32_t fb[2][2];
        uint32_t krow = q * 16 + (lane & 15);
#pragma unroll
        for (int t = 0; t < 2; t++) {
            uint32_t ncol = (wid * 2 + t) * 8;
            ldsm2t(mb + (krow * 136 + ncol) * 2, fb[t]);
        }
        int mlo = (q - 2 > 0) ? q - 2 : 0;
        int mhi = (q < 3) ? q : 3;
#pragma unroll
        for (int mi = 0; mi < 4; mi++) {
            if (mi < mlo || mi > mhi) continue;
            int ks = q - mi;
            uint32_t row = mi * 16 + (lane & 15);
            uint32_t col = ks * 16 + ((lane >> 4) << 3);
            uint32_t fa0[4], fa1[4];
            ldsm4(a0b + (row * 56 + col) * 2, fa0);
            ldsm4(a1b + (row * 56 + col) * 2, fa1);
#pragma unroll
            for (int t = 0; t < 2; t++) {
                mma16816h(acc[mi][t], fa0, fb[t]);
                mma16816h(acc[mi][t], fa1, fb[t]);
            }
        }
    }

    int g = lane >> 2, t4 = lane & 3;
#pragma unroll
    for (int mi = 0; mi < 4; mi++) {
#pragma unroll
        for (int t = 0; t < 2; t++) {
            int col = wid * 16 + t * 8 + 2 * t4;
            int row0 = i0 + mi * 16 + g;
            size_t base0 = (size_t)(b * Nn + row0) * Kk + fc + col;
            size_t base1 = (size_t)(b * Nn + row0 + 8) * Kk + fc + col;
            float2 sg0 = *(const float2*)&sig[base0];
            float2 sg1 = *(const float2*)&sig[base1];
            float2 o0 = make_float2(0.5f * sg0.x + 0.5f * acc[mi][t][0],
                                    0.5f * sg0.y + 0.5f * acc[mi][t][1]);
            float2 o1 = make_float2(0.5f * sg1.x + 0.5f * acc[mi][t][2],
                                    0.5f * sg1.y + 0.5f * acc[mi][t][3]);
            *(float2*)&out_mem[base0] = o0;
            *(float2*)&out_mem[base1] = o1;
        }
    }
}

// ---------------- launch ----------------
extern "C" void kernel_launch(void* const* d_in, const int* in_sizes, int n_in,
                              void* d_out, int out_size) {
    const float* sig   = (const float*)d_in[0];
    const float* mem   = (const float*)d_in[1];
    const float* w     = (const float*)d_in[2];
    const float* bias  = (const float*)d_in[3];
    const float* gamma = (const float*)d_in[4];
    const float* beta  = (const float*)d_in[5];
    float* out_mem  = (float*)d_out;
    float* out_attn = (float*)d_out + (size_t)Bsz * Nn * Kk;

    static bool attr_done = false;
    if (!attr_done) {
        cudaFuncSetAttribute(k_gemm, cudaFuncAttributeMaxDynamicSharedMemorySize, GEMM_SMEM);
        cudaFuncSetAttribute(k_memw, cudaFuncAttributeMaxDynamicSharedMemorySize, MW_SMEM);
        attr_done = true;
    }

    k_wsplit<<<192, 256>>>(w);                               // launch 0
    k_gemm<<<Mm / 128, 256, GEMM_SMEM>>>(sig, mem, bias);    // launch 1
    k_attn<<<dim3(Nn / 16, Bsz), 256>>>(gamma, beta, out_attn); // launch 2
    k_memw<<<dim3(Nn / 64, 24, Bsz), 256, MW_SMEM>>>(sig, mem, out_mem); // launch 3
}